// round 8
// baseline (speedup 1.0000x reference)
#include <cuda_runtime.h>
#include <math.h>
#include <stdint.h>

// Problem constants
#define BATCH 4
#define TSEQ  2048
#define CDIM  1024
#define NHEAD 16
#define HDIM  64
#define MROWS (BATCH * TSEQ)   // 8192

// Scratch (device globals: allocation-guard safe)
__device__ float g_q[MROWS * CDIM];
__device__ float g_k[MROWS * CDIM];
__device__ float g_v[MROWS * CDIM];
__device__ float g_ctx[MROWS * CDIM];
__device__ float g_wt[4 * CDIM * CDIM];   // transposed tf32 weights [n][k]

__device__ __forceinline__ uint32_t f32_to_tf32(float x) {
    uint32_t u;
    asm("cvt.rna.tf32.f32 %0, %1;" : "=r"(u) : "f"(x));
    return u;
}

// ---------------------------------------------------------------------------
// Weight transpose + tf32 round: g_wt[mat][n][k] = tf32(W[mat][k][n])
// ---------------------------------------------------------------------------
__global__ void transpose_w(const float* __restrict__ W0, const float* __restrict__ W1,
                            const float* __restrict__ W2, const float* __restrict__ W3)
{
    __shared__ float t[32][33];
    const int z = blockIdx.z;
    const float* W = (z == 0) ? W0 : (z == 1) ? W1 : (z == 2) ? W2 : W3;
    float* o = g_wt + (size_t)z * CDIM * CDIM;
    const int k0 = blockIdx.x * 32, n0 = blockIdx.y * 32;
    const int tx = threadIdx.x, ty = threadIdx.y;   // 32 x 8
#pragma unroll
    for (int i = 0; i < 32; i += 8)
        t[ty + i][tx] = W[(size_t)(k0 + ty + i) * CDIM + n0 + tx];
    __syncthreads();
#pragma unroll
    for (int i = 0; i < 32; i += 8) {
        uint32_t u = f32_to_tf32(t[tx][ty + i]);
        o[(size_t)(n0 + ty + i) * CDIM + k0 + tx] = __uint_as_float(u);
    }
}

// ---------------------------------------------------------------------------
// tf32 mma.sync GEMM: C[M,N] = A[M,K] @ W[K,N] + bias
// BM=BN=128, BK=32, 256 threads (8 warps, each a 32x64 warp tile).
// A row-major tf32 in smem [128][36]; B (= Wt[n][k]) col-major tf32 [128][36].
// mode 0: A = x, Wt/bias/out selected by blockIdx.z (q/k/v), scatter [B,H,T,D]
// mode 1: A = g_ctx, Wt = g_wt[3], bias=bo, out row-major (d_out)
// ---------------------------------------------------------------------------
#define BK 32
#define NCHUNK (CDIM / BK)          // 32
#define TSTRIDE 36                  // padded floats per row
#define TILE_F (128 * TSTRIDE)      // floats per tile buffer
#define SMEM_DYN (4 * TILE_F * 4)   // 2 stages x (A+B) = 73728 B

__device__ __forceinline__ void mma_tf32(float* c, const uint32_t* a, const uint32_t* b) {
    asm volatile(
        "mma.sync.aligned.m16n8k8.row.col.f32.tf32.tf32.f32 "
        "{%0,%1,%2,%3}, {%4,%5,%6,%7}, {%8,%9}, {%0,%1,%2,%3};"
        : "+f"(c[0]), "+f"(c[1]), "+f"(c[2]), "+f"(c[3])
        : "r"(a[0]), "r"(a[1]), "r"(a[2]), "r"(a[3]), "r"(b[0]), "r"(b[1]));
}

__global__ __launch_bounds__(256)
void gemm_tf32(const float* __restrict__ Ain,
               const float* __restrict__ bq, const float* __restrict__ bk,
               const float* __restrict__ bv,
               float* __restrict__ outp, int mode)
{
    extern __shared__ float sm[];

    const int tid = threadIdx.x;
    const int wid = tid >> 5, lane = tid & 31;
    const int bx = blockIdx.x, by = blockIdx.y, bz = blockIdx.z;

    const float* A;
    const float* Wt;
    const float* bias;
    float* O;
    if (mode == 0) {
        A = Ain;
        Wt = g_wt + (size_t)bz * CDIM * CDIM;
        bias = (bz == 0) ? bq : (bz == 1) ? bk : bv;
        O = (bz == 0) ? g_q : (bz == 1) ? g_k : g_v;
    } else {
        A = g_ctx;
        Wt = g_wt + (size_t)3 * CDIM * CDIM;
        bias = bq;
        O = outp;
    }

    const float* Abase = A  + (size_t)(by * 128) * CDIM;
    const float* Bbase = Wt + (size_t)(bx * 128) * CDIM;

    // load mapping: 1024 float4 per matrix tile, 4 per thread
    const int lr  = tid >> 1;          // 0..127 row (2 threads/row)? no:
    (void)lr;
    // e = tid + i*256, r = e>>3 (0..127), c4 = e&7 (float4 col)

    float4 pa[4], pb[4];
    auto ldg_tile = [&](int c) {
        const float* Ag = Abase + c * BK;
        const float* Bg = Bbase + c * BK;
#pragma unroll
        for (int i = 0; i < 4; i++) {
            int e = tid + i * 256;
            int r = e >> 3, c4 = e & 7;
            pa[i] = *(const float4*)(Ag + (size_t)r * CDIM + c4 * 4);
            pb[i] = *(const float4*)(Bg + (size_t)r * CDIM + c4 * 4);
        }
    };
    auto sts_tile = [&](int s) {
        float* As = sm + (size_t)s * TILE_F;
        float* Bs = sm + (size_t)(2 + s) * TILE_F;
#pragma unroll
        for (int i = 0; i < 4; i++) {
            int e = tid + i * 256;
            int r = e >> 3, c4 = e & 7;
            float* ap = As + r * TSTRIDE + c4 * 4;
            ap[0] = __uint_as_float(f32_to_tf32(pa[i].x));
            ap[1] = __uint_as_float(f32_to_tf32(pa[i].y));
            ap[2] = __uint_as_float(f32_to_tf32(pa[i].z));
            ap[3] = __uint_as_float(f32_to_tf32(pa[i].w));
            float* bp = Bs + r * TSTRIDE + c4 * 4;
            bp[0] = pb[i].x; bp[1] = pb[i].y; bp[2] = pb[i].z; bp[3] = pb[i].w;
        }
    };

    // warp tile: 32 (M) x 64 (N)
    const int m0w = (wid >> 1) * 32;
    const int n0w = (wid & 1) * 64;
    const int lq = lane >> 2;          // 0..7
    const int lr4 = lane & 3;          // 0..3

    float acc[2][8][4];
#pragma unroll
    for (int mi = 0; mi < 2; mi++)
#pragma unroll
        for (int ni = 0; ni < 8; ni++)
#pragma unroll
            for (int j = 0; j < 4; j++) acc[mi][ni][j] = 0.f;

    ldg_tile(0);
    sts_tile(0);
    __syncthreads();

    for (int c = 0; c < NCHUNK; c++) {
        if (c + 1 < NCHUNK) ldg_tile(c + 1);

        const uint32_t* As = (const uint32_t*)(sm + (size_t)(c & 1) * TILE_F);
        const uint32_t* Bs = (const uint32_t*)(sm + (size_t)(2 + (c & 1)) * TILE_F);

#pragma unroll
        for (int kk = 0; kk < BK; kk += 8) {
            uint32_t af[2][4], bf[8][2];
#pragma unroll
            for (int mi = 0; mi < 2; mi++) {
                int row = m0w + mi * 16 + lq;
                af[mi][0] = As[row * TSTRIDE + kk + lr4];
                af[mi][1] = As[(row + 8) * TSTRIDE + kk + lr4];
                af[mi][2] = As[row * TSTRIDE + kk + 4 + lr4];
                af[mi][3] = As[(row + 8) * TSTRIDE + kk + 4 + lr4];
            }
#pragma unroll
            for (int ni = 0; ni < 8; ni++) {
                int col = n0w + ni * 8 + lq;
                bf[ni][0] = Bs[col * TSTRIDE + kk + lr4];
                bf[ni][1] = Bs[col * TSTRIDE + kk + 4 + lr4];
            }
#pragma unroll
            for (int mi = 0; mi < 2; mi++)
#pragma unroll
                for (int ni = 0; ni < 8; ni++)
                    mma_tf32(acc[mi][ni], af[mi], bf[ni]);
        }

        if (c + 1 < NCHUNK) {
            sts_tile((c + 1) & 1);
            __syncthreads();
        }
    }

    // Epilogue: bias + store (float2 per fragment row)
#pragma unroll
    for (int mi = 0; mi < 2; mi++) {
#pragma unroll
        for (int ni = 0; ni < 8; ni++) {
            int n = bx * 128 + n0w + ni * 8 + 2 * lr4;
            float bx0 = __ldg(&bias[n]), bx1 = __ldg(&bias[n + 1]);
            int m = by * 128 + m0w + mi * 16 + lq;
            float2 v0 = make_float2(acc[mi][ni][0] + bx0, acc[mi][ni][1] + bx1);
            float2 v1 = make_float2(acc[mi][ni][2] + bx0, acc[mi][ni][3] + bx1);
            size_t g0, g1;
            if (mode == 0) {
                int h = n >> 6, d = n & (HDIM - 1);
                int b0 = m >> 11, t0 = m & (TSEQ - 1);
                int b1 = (m + 8) >> 11, t1 = (m + 8) & (TSEQ - 1);
                g0 = (((size_t)(b0 * NHEAD + h) * TSEQ + t0) * HDIM) + d;
                g1 = (((size_t)(b1 * NHEAD + h) * TSEQ + t1) * HDIM) + d;
            } else {
                g0 = (size_t)m * CDIM + n;
                g1 = (size_t)(m + 8) * CDIM + n;
            }
            *(float2*)(O + g0) = v0;
            *(float2*)(O + g1) = v1;
        }
    }
}

// ---------------------------------------------------------------------------
// Causal attention, fp32, online softmax (unchanged — passed round 4).
// ---------------------------------------------------------------------------
__global__ __launch_bounds__(128)
void attn_kernel()
{
    const int bh  = blockIdx.y;
    const int qb  = (gridDim.x - 1) - blockIdx.x;
    const int tid = threadIdx.x;
    const int qi  = qb * 128 + tid;
    const float scale = 0.125f;

    __shared__ float4 Ks[64][16];
    __shared__ float4 Vs[64][16];

    const float4* qptr = (const float4*)(g_q + ((size_t)bh * TSEQ + qi) * HDIM);
    float4 qv[16], ov[16];
#pragma unroll
    for (int d = 0; d < 16; d++) {
        qv[d] = qptr[d];
        ov[d] = make_float4(0.f, 0.f, 0.f, 0.f);
    }
    float m = -1e30f, l = 0.f;

    const int ntiles = 2 * qb + 2;
    const float4* kbase = (const float4*)(g_k + (size_t)bh * TSEQ * HDIM);
    const float4* vbase = (const float4*)(g_v + (size_t)bh * TSEQ * HDIM);

    for (int t0 = 0; t0 < ntiles; t0++) {
        const int j0 = t0 * 64;
        const float4* kp = kbase + (size_t)j0 * 16;
        const float4* vp = vbase + (size_t)j0 * 16;
#pragma unroll
        for (int it = 0; it < 8; it++) {
            int idx = tid + it * 128;
            ((float4*)Ks)[idx] = kp[idx];
            ((float4*)Vs)[idx] = vp[idx];
        }
        __syncthreads();

        int jmax = qi - j0 + 1;
        if (jmax > 64) jmax = 64;
        for (int j = 0; j < jmax; j++) {
            float4 a = make_float4(0.f, 0.f, 0.f, 0.f);
#pragma unroll
            for (int d = 0; d < 16; d++) {
                float4 kv = Ks[j][d];
                a.x = fmaf(qv[d].x, kv.x, a.x);
                a.y = fmaf(qv[d].y, kv.y, a.y);
                a.z = fmaf(qv[d].z, kv.z, a.z);
                a.w = fmaf(qv[d].w, kv.w, a.w);
            }
            float s = ((a.x + a.y) + (a.z + a.w)) * scale;

            if (s > m) {
                float corr = __expf(m - s);
                m = s;
                l *= corr;
#pragma unroll
                for (int d = 0; d < 16; d++) {
                    ov[d].x *= corr; ov[d].y *= corr;
                    ov[d].z *= corr; ov[d].w *= corr;
                }
            }
            float p = __expf(s - m);
            l += p;
#pragma unroll
            for (int d = 0; d < 16; d++) {
                float4 vv = Vs[j][d];
                ov[d].x = fmaf(p, vv.x, ov[d].x);
                ov[d].y = fmaf(p, vv.y, ov[d].y);
                ov[d].z = fmaf(p, vv.z, ov[d].z);
                ov[d].w = fmaf(p, vv.w, ov[d].w);
            }
        }
        __syncthreads();
    }

    const float inv = 1.f / l;
    float4* obase = (float4*)(g_ctx
        + ((size_t)(bh >> 4) * TSEQ + qi) * CDIM + (bh & 15) * HDIM);
#pragma unroll
    for (int d = 0; d < 16; d++) {
        float4 o = ov[d];
        o.x *= inv; o.y *= inv; o.z *= inv; o.w *= inv;
        obase[d] = o;
    }
}

// ---------------------------------------------------------------------------
// kernel_launch: transpose -> QKV GEMM (fused) -> attention -> O GEMM
// ---------------------------------------------------------------------------
extern "C" void kernel_launch(void* const* d_in, const int* in_sizes, int n_in,
                              void* d_out, int out_size)
{
    const float* x  = (const float*)d_in[0];
    const float* Wq = (const float*)d_in[1];
    const float* bq = (const float*)d_in[2];
    const float* Wk = (const float*)d_in[3];
    const float* bk = (const float*)d_in[4];
    const float* Wv = (const float*)d_in[5];
    const float* bv = (const float*)d_in[6];
    const float* Wo = (const float*)d_in[7];
    const float* bo = (const float*)d_in[8];
    float* out = (float*)d_out;

    cudaFuncSetAttribute(gemm_tf32, cudaFuncAttributeMaxDynamicSharedMemorySize, SMEM_DYN);

    dim3 tgrid(CDIM / 32, CDIM / 32, 4);
    transpose_w<<<tgrid, dim3(32, 8)>>>(Wq, Wk, Wv, Wo);

    dim3 qkv_grid(CDIM / 128, MROWS / 128, 3);   // (8, 64, 3)
    gemm_tf32<<<qkv_grid, 256, SMEM_DYN>>>(x, bq, bk, bv, nullptr, 0);

    dim3 agrid(TSEQ / 128, BATCH * NHEAD);       // (16, 64)
    attn_kernel<<<agrid, 128>>>();

    dim3 o_grid(CDIM / 128, MROWS / 128, 1);     // (8, 64)
    gemm_tf32<<<o_grid, 256, SMEM_DYN>>>(nullptr, bo, nullptr, nullptr, out, 1);
}

// round 9
// speedup vs baseline: 2.3501x; 2.3501x over previous
#include <cuda_runtime.h>
#include <math.h>
#include <stdint.h>

// Problem constants
#define BATCH 4
#define TSEQ  2048
#define CDIM  1024
#define NHEAD 16
#define HDIM  64
#define MROWS (BATCH * TSEQ)   // 8192

// Scratch (device globals: allocation-guard safe)
__device__ float g_q[MROWS * CDIM];
__device__ float g_k[MROWS * CDIM];
__device__ float g_v[MROWS * CDIM];
__device__ float g_ctx[MROWS * CDIM];
__device__ float g_wt[4 * CDIM * CDIM];   // transposed tf32 weights [n][k]

__device__ __forceinline__ uint32_t f32_to_tf32(float x) {
    uint32_t u;
    asm("cvt.rna.tf32.f32 %0, %1;" : "=r"(u) : "f"(x));
    return u;
}

// Fast exp2 on the FMA pipe (no MUFU). Valid for f <= 0, clamped at -120.
// Max rel err ~4e-5 on r in [-0.5, 0.5].
__device__ __forceinline__ float exp2fast(float f) {
    f = fmaxf(f, -120.f);
    float t = __fadd_rn(f, 12582912.f);           // round-to-nearest int
    int i = __float_as_int(t) << 23;
    float r = __fsub_rn(f, __fsub_rn(t, 12582912.f));
    float p = 0.0096181291f;
    p = __fmaf_rn(p, r, 0.055504109f);
    p = __fmaf_rn(p, r, 0.24022651f);
    p = __fmaf_rn(p, r, 0.69314718f);
    p = __fmaf_rn(p, r, 1.0f);
    return __int_as_float(__float_as_int(p) + i);
}

__device__ __forceinline__ void mma_tf32(float* c, const uint32_t* a, const uint32_t* b) {
    asm volatile(
        "mma.sync.aligned.m16n8k8.row.col.f32.tf32.tf32.f32 "
        "{%0,%1,%2,%3}, {%4,%5,%6,%7}, {%8,%9}, {%0,%1,%2,%3};"
        : "+f"(c[0]), "+f"(c[1]), "+f"(c[2]), "+f"(c[3])
        : "r"(a[0]), "r"(a[1]), "r"(a[2]), "r"(a[3]), "r"(b[0]), "r"(b[1]));
}

// ---------------------------------------------------------------------------
// Weight transpose + tf32 round: g_wt[mat][n][k] = tf32(W[mat][k][n])
// ---------------------------------------------------------------------------
__global__ void transpose_w(const float* __restrict__ W0, const float* __restrict__ W1,
                            const float* __restrict__ W2, const float* __restrict__ W3)
{
    __shared__ float t[32][33];
    const int z = blockIdx.z;
    const float* W = (z == 0) ? W0 : (z == 1) ? W1 : (z == 2) ? W2 : W3;
    float* o = g_wt + (size_t)z * CDIM * CDIM;
    const int k0 = blockIdx.x * 32, n0 = blockIdx.y * 32;
    const int tx = threadIdx.x, ty = threadIdx.y;   // 32 x 8
#pragma unroll
    for (int i = 0; i < 32; i += 8)
        t[ty + i][tx] = W[(size_t)(k0 + ty + i) * CDIM + n0 + tx];
    __syncthreads();
#pragma unroll
    for (int i = 0; i < 32; i += 8) {
        uint32_t u = f32_to_tf32(t[tx][ty + i]);
        o[(size_t)(n0 + ty + i) * CDIM + k0 + tx] = __uint_as_float(u);
    }
}

// ---------------------------------------------------------------------------
// tf32 mma.sync GEMM (unchanged from round 8 — passing)
// ---------------------------------------------------------------------------
#define BK 32
#define NCHUNK (CDIM / BK)          // 32
#define TSTRIDE 36
#define TILE_F (128 * TSTRIDE)
#define SMEM_DYN (4 * TILE_F * 4)

__global__ __launch_bounds__(256)
void gemm_tf32(const float* __restrict__ Ain,
               const float* __restrict__ bq, const float* __restrict__ bk,
               const float* __restrict__ bv,
               float* __restrict__ outp, int mode)
{
    extern __shared__ float sm[];

    const int tid = threadIdx.x;
    const int wid = tid >> 5, lane = tid & 31;
    const int bx = blockIdx.x, by = blockIdx.y, bz = blockIdx.z;

    const float* A;
    const float* Wt;
    const float* bias;
    float* O;
    if (mode == 0) {
        A = Ain;
        Wt = g_wt + (size_t)bz * CDIM * CDIM;
        bias = (bz == 0) ? bq : (bz == 1) ? bk : bv;
        O = (bz == 0) ? g_q : (bz == 1) ? g_k : g_v;
    } else {
        A = g_ctx;
        Wt = g_wt + (size_t)3 * CDIM * CDIM;
        bias = bq;
        O = outp;
    }

    const float* Abase = A  + (size_t)(by * 128) * CDIM;
    const float* Bbase = Wt + (size_t)(bx * 128) * CDIM;

    float4 pa[4], pb[4];
    auto ldg_tile = [&](int c) {
        const float* Ag = Abase + c * BK;
        const float* Bg = Bbase + c * BK;
#pragma unroll
        for (int i = 0; i < 4; i++) {
            int e = tid + i * 256;
            int r = e >> 3, c4 = e & 7;
            pa[i] = *(const float4*)(Ag + (size_t)r * CDIM + c4 * 4);
            pb[i] = *(const float4*)(Bg + (size_t)r * CDIM + c4 * 4);
        }
    };
    auto sts_tile = [&](int s) {
        float* As = sm + (size_t)s * TILE_F;
        float* Bs = sm + (size_t)(2 + s) * TILE_F;
#pragma unroll
        for (int i = 0; i < 4; i++) {
            int e = tid + i * 256;
            int r = e >> 3, c4 = e & 7;
            float* ap = As + r * TSTRIDE + c4 * 4;
            ap[0] = __uint_as_float(f32_to_tf32(pa[i].x));
            ap[1] = __uint_as_float(f32_to_tf32(pa[i].y));
            ap[2] = __uint_as_float(f32_to_tf32(pa[i].z));
            ap[3] = __uint_as_float(f32_to_tf32(pa[i].w));
            float* bp = Bs + r * TSTRIDE + c4 * 4;
            bp[0] = pb[i].x; bp[1] = pb[i].y; bp[2] = pb[i].z; bp[3] = pb[i].w;
        }
    };

    const int m0w = (wid >> 1) * 32;
    const int n0w = (wid & 1) * 64;
    const int lq = lane >> 2;
    const int lr4 = lane & 3;

    float acc[2][8][4];
#pragma unroll
    for (int mi = 0; mi < 2; mi++)
#pragma unroll
        for (int ni = 0; ni < 8; ni++)
#pragma unroll
            for (int j = 0; j < 4; j++) acc[mi][ni][j] = 0.f;

    ldg_tile(0);
    sts_tile(0);
    __syncthreads();

    for (int c = 0; c < NCHUNK; c++) {
        if (c + 1 < NCHUNK) ldg_tile(c + 1);

        const uint32_t* As = (const uint32_t*)(sm + (size_t)(c & 1) * TILE_F);
        const uint32_t* Bs = (const uint32_t*)(sm + (size_t)(2 + (c & 1)) * TILE_F);

#pragma unroll
        for (int kk = 0; kk < BK; kk += 8) {
            uint32_t af[2][4], bf[8][2];
#pragma unroll
            for (int mi = 0; mi < 2; mi++) {
                int row = m0w + mi * 16 + lq;
                af[mi][0] = As[row * TSTRIDE + kk + lr4];
                af[mi][1] = As[(row + 8) * TSTRIDE + kk + lr4];
                af[mi][2] = As[row * TSTRIDE + kk + 4 + lr4];
                af[mi][3] = As[(row + 8) * TSTRIDE + kk + 4 + lr4];
            }
#pragma unroll
            for (int ni = 0; ni < 8; ni++) {
                int col = n0w + ni * 8 + lq;
                bf[ni][0] = Bs[col * TSTRIDE + kk + lr4];
                bf[ni][1] = Bs[col * TSTRIDE + kk + 4 + lr4];
            }
#pragma unroll
            for (int mi = 0; mi < 2; mi++)
#pragma unroll
                for (int ni = 0; ni < 8; ni++)
                    mma_tf32(acc[mi][ni], af[mi], bf[ni]);
        }

        if (c + 1 < NCHUNK) {
            sts_tile((c + 1) & 1);
            __syncthreads();
        }
    }

#pragma unroll
    for (int mi = 0; mi < 2; mi++) {
#pragma unroll
        for (int ni = 0; ni < 8; ni++) {
            int n = bx * 128 + n0w + ni * 8 + 2 * lr4;
            float bx0 = __ldg(&bias[n]), bx1 = __ldg(&bias[n + 1]);
            int m = by * 128 + m0w + mi * 16 + lq;
            float2 v0 = make_float2(acc[mi][ni][0] + bx0, acc[mi][ni][1] + bx1);
            float2 v1 = make_float2(acc[mi][ni][2] + bx0, acc[mi][ni][3] + bx1);
            size_t g0, g1;
            if (mode == 0) {
                int h = n >> 6, d = n & (HDIM - 1);
                int b0 = m >> 11, t0 = m & (TSEQ - 1);
                int b1 = (m + 8) >> 11, t1 = (m + 8) & (TSEQ - 1);
                g0 = (((size_t)(b0 * NHEAD + h) * TSEQ + t0) * HDIM) + d;
                g1 = (((size_t)(b1 * NHEAD + h) * TSEQ + t1) * HDIM) + d;
            } else {
                g0 = (size_t)m * CDIM + n;
                g1 = (size_t)(m + 8) * CDIM + n;
            }
            *(float2*)(O + g0) = v0;
            *(float2*)(O + g1) = v1;
        }
    }
}

// ---------------------------------------------------------------------------
// Tensor-core flash attention (tf32 mma.sync), FMA-pipe softmax.
// Grid (T/64, B*H), 128 threads = 4 warps, 16 query rows per warp.
// ---------------------------------------------------------------------------
#define ASTRIDE 68                       // K, P, Q-staging smem stride (floats)
#define VSTRIDE 72                       // V smem stride
#define K_OFF 0
#define V_OFF (64 * ASTRIDE)             // 4352
#define P_OFF (V_OFF + 64 * VSTRIDE)     // 8960
#define ATTN_SMEM_B ((P_OFF + 64 * ASTRIDE) * 4)   // 53248 bytes

__global__ __launch_bounds__(128)
void attn_mma()
{
    extern __shared__ float sm[];
    float* Ks = sm + K_OFF;
    float* Vs = sm + V_OFF;
    float* Ps = sm + P_OFF;

    const int tid  = threadIdx.x;
    const int wid  = tid >> 5, lane = tid & 31;
    const int lq   = lane >> 2, lr4 = lane & 3;
    const int bh   = blockIdx.y;
    const int qtile = (gridDim.x - 1) - blockIdx.x;   // largest-first
    const int qi0  = qtile * 64;
    const int m0w  = wid * 16;

    const float* Qg = g_q + ((size_t)bh * TSEQ + qi0) * HDIM;
    const float* Kg = g_k + (size_t)bh * TSEQ * HDIM;
    const float* Vg = g_v + (size_t)bh * TSEQ * HDIM;

    // Stage Q tile (64x64) through Ks, pull A-fragments into registers.
#pragma unroll
    for (int i = 0; i < 8; i++) {
        int e = tid + i * 128;
        int r = e >> 4, c4 = e & 15;
        float4 v = *(const float4*)(Qg + (size_t)r * HDIM + c4 * 4);
        float* p = Ks + r * ASTRIDE + c4 * 4;
        p[0] = __uint_as_float(f32_to_tf32(v.x));
        p[1] = __uint_as_float(f32_to_tf32(v.y));
        p[2] = __uint_as_float(f32_to_tf32(v.z));
        p[3] = __uint_as_float(f32_to_tf32(v.w));
    }
    __syncthreads();

    uint32_t qa[8][4];
    {
        const uint32_t* Q32 = (const uint32_t*)Ks;
#pragma unroll
        for (int c = 0; c < 8; c++) {
            qa[c][0] = Q32[(m0w + lq)     * ASTRIDE + c * 8 + lr4];
            qa[c][1] = Q32[(m0w + lq + 8) * ASTRIDE + c * 8 + lr4];
            qa[c][2] = Q32[(m0w + lq)     * ASTRIDE + c * 8 + 4 + lr4];
            qa[c][3] = Q32[(m0w + lq + 8) * ASTRIDE + c * 8 + 4 + lr4];
        }
    }

    float oacc[8][4];
#pragma unroll
    for (int nb = 0; nb < 8; nb++)
#pragma unroll
        for (int j = 0; j < 4; j++) oacc[nb][j] = 0.f;
    float m0 = -1e30f, m1 = -1e30f, l0 = 0.f, l1 = 0.f;
    const float k2 = 0.125f * 1.4426950408889634f;   // scale * log2(e)

    const int ntiles = qtile + 1;
    for (int kt = 0; kt < ntiles; kt++) {
        __syncthreads();   // previous iter's smem reads done

        const float* Kt = Kg + (size_t)kt * 64 * HDIM;
        const float* Vt = Vg + (size_t)kt * 64 * HDIM;
#pragma unroll
        for (int i = 0; i < 8; i++) {
            int e = tid + i * 128;
            int r = e >> 4, c4 = e & 15;
            float4 kv = *(const float4*)(Kt + (size_t)r * HDIM + c4 * 4);
            float* kp = Ks + r * ASTRIDE + c4 * 4;
            kp[0] = __uint_as_float(f32_to_tf32(kv.x));
            kp[1] = __uint_as_float(f32_to_tf32(kv.y));
            kp[2] = __uint_as_float(f32_to_tf32(kv.z));
            kp[3] = __uint_as_float(f32_to_tf32(kv.w));
            float4 vv = *(const float4*)(Vt + (size_t)r * HDIM + c4 * 4);
            float* vp = Vs + r * VSTRIDE + c4 * 4;
            vp[0] = __uint_as_float(f32_to_tf32(vv.x));
            vp[1] = __uint_as_float(f32_to_tf32(vv.y));
            vp[2] = __uint_as_float(f32_to_tf32(vv.z));
            vp[3] = __uint_as_float(f32_to_tf32(vv.w));
        }
        __syncthreads();

        // S = Q @ K^T  (16x64 per warp)
        float sacc[8][4];
#pragma unroll
        for (int nb = 0; nb < 8; nb++)
#pragma unroll
            for (int j = 0; j < 4; j++) sacc[nb][j] = 0.f;

        {
            const uint32_t* Ku = (const uint32_t*)Ks;
#pragma unroll
            for (int c = 0; c < 8; c++) {
#pragma unroll
                for (int nb = 0; nb < 8; nb++) {
                    uint32_t b[2];
                    b[0] = Ku[(nb * 8 + lq) * ASTRIDE + c * 8 + lr4];
                    b[1] = Ku[(nb * 8 + lq) * ASTRIDE + c * 8 + 4 + lr4];
                    mma_tf32(sacc[nb], qa[c], b);
                }
            }
        }

        // Causal mask (diagonal tile only)
        if (kt == qtile) {
            int row0 = m0w + lq, row1 = row0 + 8;
#pragma unroll
            for (int nb = 0; nb < 8; nb++) {
                int col0 = nb * 8 + 2 * lr4;
                if (col0     > row0) sacc[nb][0] = -1e30f;
                if (col0 + 1 > row0) sacc[nb][1] = -1e30f;
                if (col0     > row1) sacc[nb][2] = -1e30f;
                if (col0 + 1 > row1) sacc[nb][3] = -1e30f;
            }
        }

        // Online softmax (base-2, FMA-pipe exp)
        float vm0 = -1e30f, vm1 = -1e30f;
#pragma unroll
        for (int nb = 0; nb < 8; nb++) {
            vm0 = fmaxf(vm0, fmaxf(sacc[nb][0], sacc[nb][1]));
            vm1 = fmaxf(vm1, fmaxf(sacc[nb][2], sacc[nb][3]));
        }
        vm0 = fmaxf(vm0, __shfl_xor_sync(0xffffffffu, vm0, 1));
        vm0 = fmaxf(vm0, __shfl_xor_sync(0xffffffffu, vm0, 2));
        vm1 = fmaxf(vm1, __shfl_xor_sync(0xffffffffu, vm1, 1));
        vm1 = fmaxf(vm1, __shfl_xor_sync(0xffffffffu, vm1, 2));

        float mn0 = fmaxf(m0, vm0), mn1 = fmaxf(m1, vm1);
        float a0 = exp2fast((m0 - mn0) * k2);
        float a1 = exp2fast((m1 - mn1) * k2);
        m0 = mn0; m1 = mn1;

        float rs0 = 0.f, rs1 = 0.f;
        {
            float* P0 = Ps + (m0w + lq) * ASTRIDE + 2 * lr4;
            float* P1 = P0 + 8 * ASTRIDE;
#pragma unroll
            for (int nb = 0; nb < 8; nb++) {
                float p0 = exp2fast((sacc[nb][0] - mn0) * k2);
                float p1 = exp2fast((sacc[nb][1] - mn0) * k2);
                float p2 = exp2fast((sacc[nb][2] - mn1) * k2);
                float p3 = exp2fast((sacc[nb][3] - mn1) * k2);
                rs0 += p0 + p1;
                rs1 += p2 + p3;
                float2 w0 = make_float2(__uint_as_float(f32_to_tf32(p0)),
                                        __uint_as_float(f32_to_tf32(p1)));
                float2 w1 = make_float2(__uint_as_float(f32_to_tf32(p2)),
                                        __uint_as_float(f32_to_tf32(p3)));
                *(float2*)(P0 + nb * 8) = w0;
                *(float2*)(P1 + nb * 8) = w1;
            }
        }
        rs0 += __shfl_xor_sync(0xffffffffu, rs0, 1);
        rs0 += __shfl_xor_sync(0xffffffffu, rs0, 2);
        rs1 += __shfl_xor_sync(0xffffffffu, rs1, 1);
        rs1 += __shfl_xor_sync(0xffffffffu, rs1, 2);
        l0 = l0 * a0 + rs0;
        l1 = l1 * a1 + rs1;
#pragma unroll
        for (int nb = 0; nb < 8; nb++) {
            oacc[nb][0] *= a0; oacc[nb][1] *= a0;
            oacc[nb][2] *= a1; oacc[nb][3] *= a1;
        }
        __syncwarp();

        // O += P @ V  (16x64 per warp, K=64 keys)
        {
            const uint32_t* Pu = (const uint32_t*)Ps;
            const uint32_t* Vu = (const uint32_t*)Vs;
#pragma unroll
            for (int c = 0; c < 8; c++) {
                uint32_t pa[4];
                pa[0] = Pu[(m0w + lq)     * ASTRIDE + c * 8 + lr4];
                pa[1] = Pu[(m0w + lq + 8) * ASTRIDE + c * 8 + lr4];
                pa[2] = Pu[(m0w + lq)     * ASTRIDE + c * 8 + 4 + lr4];
                pa[3] = Pu[(m0w + lq + 8) * ASTRIDE + c * 8 + 4 + lr4];
#pragma unroll
                for (int nb = 0; nb < 8; nb++) {
                    uint32_t b[2];
                    b[0] = Vu[(c * 8 + lr4)     * VSTRIDE + nb * 8 + lq];
                    b[1] = Vu[(c * 8 + 4 + lr4) * VSTRIDE + nb * 8 + lq];
                    mma_tf32(oacc[nb], pa, b);
                }
            }
        }
    }

    // Epilogue: normalize and store to g_ctx [B,T,C]
    float inv0 = 1.f / l0, inv1 = 1.f / l1;
    int b = bh >> 4, h = bh & 15;
    int row0 = qi0 + m0w + lq;
    float* C0 = g_ctx + ((size_t)b * TSEQ + row0) * CDIM + h * HDIM + 2 * lr4;
    float* C1 = C0 + (size_t)8 * CDIM;
#pragma unroll
    for (int nb = 0; nb < 8; nb++) {
        *(float2*)(C0 + nb * 8) = make_float2(oacc[nb][0] * inv0, oacc[nb][1] * inv0);
        *(float2*)(C1 + nb * 8) = make_float2(oacc[nb][2] * inv1, oacc[nb][3] * inv1);
    }
}

// ---------------------------------------------------------------------------
// kernel_launch: transpose -> QKV GEMM -> flash attention -> O GEMM
// ---------------------------------------------------------------------------
extern "C" void kernel_launch(void* const* d_in, const int* in_sizes, int n_in,
                              void* d_out, int out_size)
{
    const float* x  = (const float*)d_in[0];
    const float* Wq = (const float*)d_in[1];
    const float* bq = (const float*)d_in[2];
    const float* Wk = (const float*)d_in[3];
    const float* bk = (const float*)d_in[4];
    const float* Wv = (const float*)d_in[5];
    const float* bv = (const float*)d_in[6];
    const float* Wo = (const float*)d_in[7];
    const float* bo = (const float*)d_in[8];
    float* out = (float*)d_out;

    cudaFuncSetAttribute(gemm_tf32, cudaFuncAttributeMaxDynamicSharedMemorySize, SMEM_DYN);
    cudaFuncSetAttribute(attn_mma, cudaFuncAttributeMaxDynamicSharedMemorySize, ATTN_SMEM_B);

    dim3 tgrid(CDIM / 32, CDIM / 32, 4);
    transpose_w<<<tgrid, dim3(32, 8)>>>(Wq, Wk, Wv, Wo);

    dim3 qkv_grid(CDIM / 128, MROWS / 128, 3);   // (8, 64, 3)
    gemm_tf32<<<qkv_grid, 256, SMEM_DYN>>>(x, bq, bk, bv, nullptr, 0);

    dim3 agrid(TSEQ / 64, BATCH * NHEAD);        // (32, 64)
    attn_mma<<<agrid, 128, ATTN_SMEM_B>>>();

    dim3 o_grid(CDIM / 128, MROWS / 128, 1);     // (8, 64)
    gemm_tf32<<<o_grid, 256, SMEM_DYN>>>(nullptr, bo, nullptr, nullptr, out, 1);
}